// round 13
// baseline (speedup 1.0000x reference)
#include <cuda_runtime.h>
#include <math.h>

#define BB   16
#define NN   16000
#define GG   128
#define NPG  (NN + GG)          /* 16128 = 63 * 256 exactly */
#define IMGW 800.0f
#define IMGH 800.0f
#define XCLIP 4.135166556742356f   /* log(1000/16) */
#define MAXWH 64.0f             /* boxes are at most 64px wide/tall */

#define NBX   12                /* 12x12 bins */
#define NBINS (NBX * NBX)
#define BINW_INV (12.0f / 800.0f)

#define GRID_X (NPG / 256)      /* 63 */
#define NBLOCKS (GRID_X * BB)   /* 1008 */

// Per-GT argmax keys: (q_bits<<32) | (0xFFFFFFFF - idx).
// Zero at module load == "no hit"; the last block consumes AND re-zeroes
// them each call, so every graph replay starts clean.
__device__ unsigned long long g_keys[BB * GG];
__device__ unsigned int       g_ticket;

__device__ __forceinline__ float4 ld4(const float* p) {
    return *reinterpret_cast<const float4*>(p);
}

// ---------------------------------------------------------------------------
// Single fused kernel. __launch_bounds__(256, 6) caps residency at 6
// blocks/SM = up to 42 regs, so ptxas keeps the R4-style ~40-reg hot loop
// instead of squeezing to 30 (the R6/R7 regression).
// ---------------------------------------------------------------------------
__global__ void __launch_bounds__(256, 6)
fused_kernel(const float* __restrict__ props,
             const float* __restrict__ gts,
             const float* __restrict__ reg,
             float* __restrict__ out_pred,
             float* __restrict__ out_labels,
             float* __restrict__ out_regt,
             float* __restrict__ out_scores) {
    __shared__ float4       sg[GG];
    __shared__ uint4        smask[NBINS];
    __shared__ unsigned int s_rank;

    const int b   = blockIdx.y;
    const int tid = threadIdx.x;
    const float* gt_b = gts + (size_t)b * GG * 4;

    for (int i = tid; i < NBINS; i += 256)
        smask[i] = make_uint4(0u, 0u, 0u, 0u);
    __syncthreads();

    // ---- prologue: GT boxes -> smem + corner-bin masks (dilated 64px) ----
    if (tid < GG) {
        float4 v = ld4(gt_b + tid * 4);
        sg[tid] = v;
        int bx0 = (int)(fmaxf(v.x - MAXWH, 0.0f) * BINW_INV);
        int bx1 = (int)(v.z * BINW_INV); if (bx1 > NBX - 1) bx1 = NBX - 1;
        int by0 = (int)(fmaxf(v.y - MAXWH, 0.0f) * BINW_INV);
        int by1 = (int)(v.w * BINW_INV); if (by1 > NBX - 1) by1 = NBX - 1;
        const unsigned bit  = 1u << (tid & 31);
        const int      word = tid >> 5;
        unsigned int* base = reinterpret_cast<unsigned int*>(smask);
        for (int by = by0; by <= by1; by++)
            for (int bx = bx0; bx <= bx1; bx++)
                atomicOr(base + (by * NBX + bx) * 4 + word, bit);
    }
    __syncthreads();

    const int p = blockIdx.x * 256 + tid;   // grid sized exactly, p < NPG
    const bool isprop = (p < NN);

    float4 a = isprop ? ld4(props + ((size_t)b * NN + p) * 4) : sg[p - NN];

    // ---- decode + clip (outputs only: fast math) ----
    {
        float4 r = ld4(reg + ((size_t)b * NPG + p) * 4);
        float pw  = a.z - a.x;
        float ph  = a.w - a.y;
        float pcx = fmaf(0.5f, pw, a.x);
        float pcy = fmaf(0.5f, ph, a.y);
        float dx = r.x * 0.1f;
        float dy = r.y * 0.1f;
        float dw = fminf(r.z * 0.2f, XCLIP);
        float dh = fminf(r.w * 0.2f, XCLIP);
        float ncx = fmaf(dx, pw, pcx);
        float ncy = fmaf(dy, ph, pcy);
        float hnw = 0.5f * __expf(dw) * pw;
        float hnh = 0.5f * __expf(dh) * ph;
        float4 o;
        o.x = fminf(fmaxf(ncx - hnw, 0.0f), IMGW);
        o.y = fminf(fmaxf(ncy - hnh, 0.0f), IMGH);
        o.z = fminf(fmaxf(ncx + hnw, 0.0f), IMGW);
        o.w = fminf(fmaxf(ncy + hnh, 0.0f), IMGH);
        *reinterpret_cast<float4*>(out_pred + ((size_t)b * NPG + p) * 4) = o;
    }

    // ---- labels + per-GT argmax (exact IoU via atomicMax) ----
    float label;
    if (!isprop) {
        label = 1.0f;   // appended GT: self-IoU == 1.0, not in argmax domain
    } else {
        const float area_a = __fmul_rn(__fsub_rn(a.z, a.x), __fsub_rn(a.w, a.y));
        float vmax = 0.0f;
        unsigned long long* keyrow = g_keys + b * GG;
        const unsigned low = 0xFFFFFFFFu - (unsigned)p;

        const int bin = (int)(a.y * BINW_INV) * NBX + (int)(a.x * BINW_INV);
        uint4 m4 = smask[bin];
        unsigned long long m0 = ((unsigned long long)m4.y << 32) | m4.x;
        unsigned long long m1 = ((unsigned long long)m4.w << 32) | m4.z;

        for (;;) {
            int g;
            if      (m0) { g =      __ffsll(m0) - 1; m0 &= m0 - 1; }
            else if (m1) { g = 63 + __ffsll(m1);     m1 &= m1 - 1; }
            else break;

            float4 gb = sg[g];
            float ltx = fmaxf(a.x, gb.x);
            float lty = fmaxf(a.y, gb.y);
            float rbx = fminf(a.z, gb.z);
            float rby = fminf(a.w, gb.w);
            float ww = __fsub_rn(rbx, ltx);
            float hh = __fsub_rn(rby, lty);
            if (ww > 0.0f && hh > 0.0f) {
                float area_b = __fmul_rn(__fsub_rn(gb.z, gb.x),
                                         __fsub_rn(gb.w, gb.y));
                float inter = __fmul_rn(ww, hh);
                float uni   = __fsub_rn(__fadd_rn(area_b, area_a), inter);
                float q     = __fdiv_rn(inter, uni);
                vmax = fmaxf(vmax, q);
                unsigned long long key =
                    ((unsigned long long)__float_as_uint(q) << 32) | low;
                atomicMax(keyrow + g, key);
            }
        }
        label = (vmax >= 0.5f) ? 1.0f : 0.0f;
    }
    out_labels[(size_t)b * NPG + p] = label;

    // ---- cheap ticket tail: 1 fence + 1 atomic per block (tid0 only) ----
    __syncthreads();
    if (tid == 0) {
        __threadfence();                     // release block's REDGs
        s_rank = atomicAdd(&g_ticket, 1u);
    }
    __syncthreads();
    if (s_rank != NBLOCKS - 1) return;

    if (tid == 0) {
        g_ticket = 0;                        // reset for next graph replay
        __threadfence();                     // acquire all blocks' REDGs
    }
    __syncthreads();

    // ---- last block: encode epilogue (2048 items, 8 per thread, MLP) ----
#pragma unroll
    for (int k = 0; k < (BB * GG) / 256; k++) {
        int i  = k * 256 + tid;
        int bb = i >> 7;
        int g  = i & (GG - 1);

        unsigned long long key = __ldcg(&g_keys[i]);
        __stcg(&g_keys[i], 0ull);            // reset for next replay
        float q = __uint_as_float((unsigned)(key >> 32));
        unsigned idx = (key == 0ull) ? 0u
                     : (0xFFFFFFFFu - (unsigned)(key & 0xFFFFFFFFull));

        float4 mp = ld4(props + ((size_t)bb * NN + idx) * 4);
        float4 gb = ld4(gts + ((size_t)bb * GG + g) * 4);

        float pw  = mp.z - mp.x;
        float ph  = mp.w - mp.y;
        float pcx = fmaf(0.5f, pw, mp.x);
        float pcy = fmaf(0.5f, ph, mp.y);
        float gw  = gb.z - gb.x;
        float gh  = gb.w - gb.y;
        float gcx = fmaf(0.5f, gw, gb.x);
        float gcy = fmaf(0.5f, gh, gb.y);

        float dx = __fdividef(10.0f * (gcx - pcx), pw);
        float dy = __fdividef(10.0f * (gcy - pcy), ph);
        float dw = 5.0f * __logf(__fdividef(gw, pw));
        float dh = 5.0f * __logf(__fdividef(gh, ph));

        float* o = out_regt + (size_t)i * 4;
        o[0] = dx; o[1] = dy; o[2] = dw; o[3] = dh;
        out_scores[i] = q;
    }
}

// ---------------------------------------------------------------------------
extern "C" void kernel_launch(void* const* d_in, const int* in_sizes, int n_in,
                              void* d_out, int out_size) {
    const float* props = (const float*)d_in[0];   // (B, N, 4)
    const float* gts   = (const float*)d_in[1];   // (B, G, 4)
    const float* reg   = (const float*)d_in[2];   // (B, N+G, 4)

    float* out        = (float*)d_out;
    float* out_pred   = out;                                  // B*(N+G)*4
    float* out_regt   = out_pred + (size_t)BB * NPG * 4;      // B*G*4
    float* out_scores = out_regt + (size_t)BB * GG * 4;       // B*G
    float* out_labels = out_scores + (size_t)BB * GG;         // B*(N+G)

    dim3 gm(GRID_X, BB);
    fused_kernel<<<gm, 256>>>(props, gts, reg,
                              out_pred, out_labels, out_regt, out_scores);
}

// round 14
// speedup vs baseline: 1.3908x; 1.3908x over previous
#include <cuda_runtime.h>
#include <math.h>

#define BB   16
#define NN   16000
#define GG   128
#define NPG  (NN + GG)          /* 16128 = 63 * 256 exactly */
#define IMGW 800.0f
#define IMGH 800.0f
#define XCLIP 4.135166556742356f   /* log(1000/16) */
#define MAXWH 64.0f             /* boxes are at most 64px wide/tall */

#define NBX   12                /* 12x12 bins */
#define NBINS (NBX * NBX)
#define BINW_INV (12.0f / 800.0f)

#define GRID_X (NPG / 256)      /* 63 */

// Per-GT argmax keys: (q_bits<<32) | (0xFFFFFFFF - idx).
// Zero at module load == "no hit"; decode_kernel consumes AND re-zeroes each
// call so every graph replay starts clean.
__device__ unsigned long long g_keys[BB * GG];

__device__ __forceinline__ float4 ld4(const float* p) {
    return *reinterpret_cast<const float4*>(p);
}

// ---------------------------------------------------------------------------
// Kernel 1: IoU — labels + per-GT argmax (exact IoU via atomicMax).
// Prologue builds corner-bin masks with WARP BALLOTS (no smem atomics,
// no zeroing pass, single barrier): word w of bin's 128-bit mask is
// ballot over warp w's 32 GT boxes.
// ---------------------------------------------------------------------------
__global__ void __launch_bounds__(256)
iou_kernel(const float* __restrict__ props,
           const float* __restrict__ gts,
           float* __restrict__ out_labels) {
    __shared__ float4 sg[GG];
    __shared__ uint4  smask[NBINS];

    const int b    = blockIdx.y;
    const int tid  = threadIdx.x;
    const int wid  = tid >> 5;
    const int lane = tid & 31;
    const float* gt_b = gts + (size_t)b * GG * 4;

    // ---- prologue: warps 0-3 build sg[] + bin masks via ballot ----
    if (wid < 4) {
        float4 v = ld4(gt_b + tid * 4);      // GT index == tid (0..127)
        sg[tid] = v;
        // dilated coverage: any proposal whose top-left corner bin overlaps
        // [x-64, z] x [y-64, w] can intersect this GT (boxes <= 64px)
        int bx0 = (int)(fmaxf(v.x - MAXWH, 0.0f) * BINW_INV);
        int bx1 = (int)(v.z * BINW_INV); if (bx1 > NBX - 1) bx1 = NBX - 1;
        int by0 = (int)(fmaxf(v.y - MAXWH, 0.0f) * BINW_INV);
        int by1 = (int)(v.w * BINW_INV); if (by1 > NBX - 1) by1 = NBX - 1;

        unsigned int* base = reinterpret_cast<unsigned int*>(smask);
        int bin = 0;
#pragma unroll
        for (int by = 0; by < NBX; by++) {
            bool yin = (by >= by0) && (by <= by1);
#pragma unroll
            for (int bx = 0; bx < NBX; bx++, bin++) {
                bool in = yin && (bx >= bx0) && (bx <= bx1);
                unsigned m = __ballot_sync(0xFFFFFFFFu, in);
                if (lane == 0) base[bin * 4 + wid] = m;
            }
        }
    }
    __syncthreads();

    const int p = blockIdx.x * 256 + tid;   // grid sized exactly, p < NPG

    float label;
    if (p >= NN) {
        label = 1.0f;   // appended GT: self-IoU == 1.0, not in argmax domain
    } else {
        float4 a = ld4(props + ((size_t)b * NN + p) * 4);
        const float area_a = __fmul_rn(__fsub_rn(a.z, a.x), __fsub_rn(a.w, a.y));
        float vmax = 0.0f;
        unsigned long long* keyrow = g_keys + b * GG;
        const unsigned low = 0xFFFFFFFFu - (unsigned)p;

        const int bin = (int)(a.y * BINW_INV) * NBX + (int)(a.x * BINW_INV);
        uint4 m4 = smask[bin];
        unsigned long long m0 = ((unsigned long long)m4.y << 32) | m4.x;
        unsigned long long m1 = ((unsigned long long)m4.w << 32) | m4.z;

        for (;;) {
            int g;
            if      (m0) { g =      __ffsll(m0) - 1; m0 &= m0 - 1; }
            else if (m1) { g = 63 + __ffsll(m1);     m1 &= m1 - 1; }
            else break;

            float4 gb = sg[g];
            float ltx = fmaxf(a.x, gb.x);
            float lty = fmaxf(a.y, gb.y);
            float rbx = fminf(a.z, gb.z);
            float rby = fminf(a.w, gb.w);
            float ww = __fsub_rn(rbx, ltx);
            float hh = __fsub_rn(rby, lty);
            if (ww > 0.0f && hh > 0.0f) {
                float area_b = __fmul_rn(__fsub_rn(gb.z, gb.x),
                                         __fsub_rn(gb.w, gb.y));
                float inter = __fmul_rn(ww, hh);
                float uni   = __fsub_rn(__fadd_rn(area_b, area_a), inter);
                float q     = __fdiv_rn(inter, uni);
                vmax = fmaxf(vmax, q);
                unsigned long long key =
                    ((unsigned long long)__float_as_uint(q) << 32) | low;
                atomicMax(keyrow + g, key);
            }
        }
        label = (vmax >= 0.5f) ? 1.0f : 0.0f;
    }
    out_labels[(size_t)b * NPG + p] = label;
}

// ---------------------------------------------------------------------------
// Kernel 2: decode+clip for all B*(N+G) boxes; its first 8 blocks (y==0)
// also run the 2048-item encode epilogue (keys -> reg_targets + roi_scores,
// then key reset). No third launch.
// ---------------------------------------------------------------------------
__global__ void __launch_bounds__(256)
decode_kernel(const float* __restrict__ props,
              const float* __restrict__ gts,
              const float* __restrict__ reg,
              float* __restrict__ out_pred,
              float* __restrict__ out_regt,
              float* __restrict__ out_scores) {
    const int b   = blockIdx.y;
    const int tid = threadIdx.x;
    const int p   = blockIdx.x * 256 + tid;

    // ---- decode + clip (outputs only: fast math) ----
    {
        float4 a = (p < NN) ? ld4(props + ((size_t)b * NN + p) * 4)
                            : ld4(gts + ((size_t)b * GG + (p - NN)) * 4);
        float4 r = ld4(reg + ((size_t)b * NPG + p) * 4);
        float pw  = a.z - a.x;
        float ph  = a.w - a.y;
        float pcx = fmaf(0.5f, pw, a.x);
        float pcy = fmaf(0.5f, ph, a.y);
        float dx = r.x * 0.1f;
        float dy = r.y * 0.1f;
        float dw = fminf(r.z * 0.2f, XCLIP);
        float dh = fminf(r.w * 0.2f, XCLIP);
        float ncx = fmaf(dx, pw, pcx);
        float ncy = fmaf(dy, ph, pcy);
        float hnw = 0.5f * __expf(dw) * pw;
        float hnh = 0.5f * __expf(dh) * ph;
        float4 o;
        o.x = fminf(fmaxf(ncx - hnw, 0.0f), IMGW);
        o.y = fminf(fmaxf(ncy - hnh, 0.0f), IMGH);
        o.z = fminf(fmaxf(ncx + hnw, 0.0f), IMGW);
        o.w = fminf(fmaxf(ncy + hnh, 0.0f), IMGH);
        *reinterpret_cast<float4*>(out_pred + ((size_t)b * NPG + p) * 4) = o;
    }

    // ---- encode epilogue, folded into the first 8 blocks ----
    if (blockIdx.y == 0 && blockIdx.x < 8) {
        int i  = blockIdx.x * 256 + tid;     // i < 2048 = BB*GG
        int bb = i >> 7;
        int g  = i & (GG - 1);

        unsigned long long key = __ldcg(&g_keys[i]);
        __stcg(&g_keys[i], 0ull);            // reset for next graph replay
        float q = __uint_as_float((unsigned)(key >> 32));
        unsigned idx = (key == 0ull) ? 0u
                     : (0xFFFFFFFFu - (unsigned)(key & 0xFFFFFFFFull));

        float4 mp = ld4(props + ((size_t)bb * NN + idx) * 4);
        float4 gb = ld4(gts + ((size_t)bb * GG + g) * 4);

        float pw  = mp.z - mp.x;
        float ph  = mp.w - mp.y;
        float pcx = fmaf(0.5f, pw, mp.x);
        float pcy = fmaf(0.5f, ph, mp.y);
        float gw  = gb.z - gb.x;
        float gh  = gb.w - gb.y;
        float gcx = fmaf(0.5f, gw, gb.x);
        float gcy = fmaf(0.5f, gh, gb.y);

        float dx = __fdividef(10.0f * (gcx - pcx), pw);
        float dy = __fdividef(10.0f * (gcy - pcy), ph);
        float dw = 5.0f * __logf(__fdividef(gw, pw));
        float dh = 5.0f * __logf(__fdividef(gh, ph));

        float* o = out_regt + (size_t)i * 4;
        o[0] = dx; o[1] = dy; o[2] = dw; o[3] = dh;
        out_scores[i] = q;
    }
}

// ---------------------------------------------------------------------------
extern "C" void kernel_launch(void* const* d_in, const int* in_sizes, int n_in,
                              void* d_out, int out_size) {
    const float* props = (const float*)d_in[0];   // (B, N, 4)
    const float* gts   = (const float*)d_in[1];   // (B, G, 4)
    const float* reg   = (const float*)d_in[2];   // (B, N+G, 4)

    float* out        = (float*)d_out;
    float* out_pred   = out;                                  // B*(N+G)*4
    float* out_regt   = out_pred + (size_t)BB * NPG * 4;      // B*G*4
    float* out_scores = out_regt + (size_t)BB * GG * 4;       // B*G
    float* out_labels = out_scores + (size_t)BB * GG;         // B*(N+G)

    dim3 gm(GRID_X, BB);
    iou_kernel<<<gm, 256>>>(props, gts, out_labels);

    decode_kernel<<<gm, 256>>>(props, gts, reg,
                               out_pred, out_regt, out_scores);
}

// round 15
// speedup vs baseline: 1.6401x; 1.1792x over previous
#include <cuda_runtime.h>
#include <math.h>

#define BB   16
#define NN   16000
#define GG   128
#define NPG  (NN + GG)          /* 16128 = 63 * 256 exactly */
#define IMGW 800.0f
#define IMGH 800.0f
#define XCLIP 4.135166556742356f   /* log(1000/16) */
#define MAXWH 64.0f             /* boxes are at most 64px wide/tall */

#define NBX   12                /* 12x12 bins */
#define NBINS (NBX * NBX)
#define BINW_INV (12.0f / 800.0f)

#define GRID_X (NPG / 256)      /* 63 */

// Per-GT argmax keys: (q_bits<<32) | (0xFFFFFFFF - idx).
// Zero at module load == "no hit"; decode_kernel consumes AND re-zeroes each
// call so every graph replay starts clean.
__device__ unsigned long long g_keys[BB * GG];

__device__ __forceinline__ float4 ld4(const float* p) {
    return *reinterpret_cast<const float4*>(p);
}

// ---------------------------------------------------------------------------
// Kernel 1: IoU — labels + per-GT argmax (exact IoU via atomicMax).
// R11 prologue (smem atomicOr bins). Funnel loop processes candidates in
// PAIRS: two independent LDS per iteration -> MLP=2 on the 29-cyc shared
// load chain. Proposal LDG hoisted above the prologue barrier.
// ---------------------------------------------------------------------------
__global__ void __launch_bounds__(256)
iou_kernel(const float* __restrict__ props,
           const float* __restrict__ gts,
           float* __restrict__ out_labels) {
    __shared__ float4 sg[GG];
    __shared__ uint4  smask[NBINS];

    const int b   = blockIdx.y;
    const int tid = threadIdx.x;
    const int p   = blockIdx.x * 256 + tid;     // grid sized exactly, p < NPG
    const float* gt_b = gts + (size_t)b * GG * 4;

    // hoisted proposal load: DRAM latency hidden behind the prologue
    float4 a;
    if (p < NN) a = ld4(props + ((size_t)b * NN + p) * 4);

    for (int i = tid; i < NBINS; i += 256)
        smask[i] = make_uint4(0u, 0u, 0u, 0u);
    __syncthreads();

    // ---- prologue: GT boxes -> smem + corner-bin masks (dilated 64px) ----
    if (tid < GG) {
        float4 v = ld4(gt_b + tid * 4);
        sg[tid] = v;
        int bx0 = (int)(fmaxf(v.x - MAXWH, 0.0f) * BINW_INV);
        int bx1 = (int)(v.z * BINW_INV); if (bx1 > NBX - 1) bx1 = NBX - 1;
        int by0 = (int)(fmaxf(v.y - MAXWH, 0.0f) * BINW_INV);
        int by1 = (int)(v.w * BINW_INV); if (by1 > NBX - 1) by1 = NBX - 1;
        const unsigned bit  = 1u << (tid & 31);
        const int      word = tid >> 5;
        unsigned int* base = reinterpret_cast<unsigned int*>(smask);
        for (int by = by0; by <= by1; by++)
            for (int bx = bx0; bx <= bx1; bx++)
                atomicOr(base + (by * NBX + bx) * 4 + word, bit);
    }
    __syncthreads();

    float label;
    if (p >= NN) {
        label = 1.0f;   // appended GT: self-IoU == 1.0, not in argmax domain
    } else {
        const float area_a = __fmul_rn(__fsub_rn(a.z, a.x), __fsub_rn(a.w, a.y));
        float vmax = 0.0f;
        unsigned long long* keyrow = g_keys + b * GG;
        const unsigned low = 0xFFFFFFFFu - (unsigned)p;

        const int bin = (int)(a.y * BINW_INV) * NBX + (int)(a.x * BINW_INV);
        uint4 m4 = smask[bin];
        unsigned long long m0 = ((unsigned long long)m4.y << 32) | m4.x;
        unsigned long long m1 = ((unsigned long long)m4.w << 32) | m4.z;

        // paired funnel: extract up to 2 candidates, issue both LDS, then math
        for (;;) {
            int g0, g1 = -1;
            if      (m0) { g0 =      __ffsll(m0) - 1; m0 &= m0 - 1; }
            else if (m1) { g0 = 63 + __ffsll(m1);     m1 &= m1 - 1; }
            else break;
            if      (m0) { g1 =      __ffsll(m0) - 1; m0 &= m0 - 1; }
            else if (m1) { g1 = 63 + __ffsll(m1);     m1 &= m1 - 1; }

            // two independent shared loads, back-to-back issue
            float4 gb0 = sg[g0];
            float4 gb1 = sg[(g1 >= 0) ? g1 : g0];

            {
                float ltx = fmaxf(a.x, gb0.x);
                float lty = fmaxf(a.y, gb0.y);
                float rbx = fminf(a.z, gb0.z);
                float rby = fminf(a.w, gb0.w);
                float ww = __fsub_rn(rbx, ltx);
                float hh = __fsub_rn(rby, lty);
                if (ww > 0.0f && hh > 0.0f) {
                    float area_b = __fmul_rn(__fsub_rn(gb0.z, gb0.x),
                                             __fsub_rn(gb0.w, gb0.y));
                    float inter = __fmul_rn(ww, hh);
                    float uni   = __fsub_rn(__fadd_rn(area_b, area_a), inter);
                    float q     = __fdiv_rn(inter, uni);
                    vmax = fmaxf(vmax, q);
                    unsigned long long key =
                        ((unsigned long long)__float_as_uint(q) << 32) | low;
                    atomicMax(keyrow + g0, key);
                }
            }
            if (g1 >= 0) {
                float ltx = fmaxf(a.x, gb1.x);
                float lty = fmaxf(a.y, gb1.y);
                float rbx = fminf(a.z, gb1.z);
                float rby = fminf(a.w, gb1.w);
                float ww = __fsub_rn(rbx, ltx);
                float hh = __fsub_rn(rby, lty);
                if (ww > 0.0f && hh > 0.0f) {
                    float area_b = __fmul_rn(__fsub_rn(gb1.z, gb1.x),
                                             __fsub_rn(gb1.w, gb1.y));
                    float inter = __fmul_rn(ww, hh);
                    float uni   = __fsub_rn(__fadd_rn(area_b, area_a), inter);
                    float q     = __fdiv_rn(inter, uni);
                    vmax = fmaxf(vmax, q);
                    unsigned long long key =
                        ((unsigned long long)__float_as_uint(q) << 32) | low;
                    atomicMax(keyrow + g1, key);
                }
            }
        }
        label = (vmax >= 0.5f) ? 1.0f : 0.0f;
    }
    out_labels[(size_t)b * NPG + p] = label;
}

// ---------------------------------------------------------------------------
// Kernel 2: decode+clip for all B*(N+G) boxes; its first 8 blocks (y==0)
// also run the 2048-item encode epilogue (keys -> reg_targets + roi_scores,
// then key reset). No third launch.
// ---------------------------------------------------------------------------
__global__ void __launch_bounds__(256)
decode_kernel(const float* __restrict__ props,
              const float* __restrict__ gts,
              const float* __restrict__ reg,
              float* __restrict__ out_pred,
              float* __restrict__ out_regt,
              float* __restrict__ out_scores) {
    const int b   = blockIdx.y;
    const int tid = threadIdx.x;
    const int p   = blockIdx.x * 256 + tid;

    // ---- decode + clip (outputs only: fast math) ----
    {
        float4 a = (p < NN) ? ld4(props + ((size_t)b * NN + p) * 4)
                            : ld4(gts + ((size_t)b * GG + (p - NN)) * 4);
        float4 r = ld4(reg + ((size_t)b * NPG + p) * 4);
        float pw  = a.z - a.x;
        float ph  = a.w - a.y;
        float pcx = fmaf(0.5f, pw, a.x);
        float pcy = fmaf(0.5f, ph, a.y);
        float dx = r.x * 0.1f;
        float dy = r.y * 0.1f;
        float dw = fminf(r.z * 0.2f, XCLIP);
        float dh = fminf(r.w * 0.2f, XCLIP);
        float ncx = fmaf(dx, pw, pcx);
        float ncy = fmaf(dy, ph, pcy);
        float hnw = 0.5f * __expf(dw) * pw;
        float hnh = 0.5f * __expf(dh) * ph;
        float4 o;
        o.x = fminf(fmaxf(ncx - hnw, 0.0f), IMGW);
        o.y = fminf(fmaxf(ncy - hnh, 0.0f), IMGH);
        o.z = fminf(fmaxf(ncx + hnw, 0.0f), IMGW);
        o.w = fminf(fmaxf(ncy + hnh, 0.0f), IMGH);
        *reinterpret_cast<float4*>(out_pred + ((size_t)b * NPG + p) * 4) = o;
    }

    // ---- encode epilogue, folded into the first 8 blocks ----
    if (blockIdx.y == 0 && blockIdx.x < 8) {
        int i  = blockIdx.x * 256 + tid;     // i < 2048 = BB*GG
        int bb = i >> 7;
        int g  = i & (GG - 1);

        unsigned long long key = __ldcg(&g_keys[i]);
        __stcg(&g_keys[i], 0ull);            // reset for next graph replay
        float q = __uint_as_float((unsigned)(key >> 32));
        unsigned idx = (key == 0ull) ? 0u
                     : (0xFFFFFFFFu - (unsigned)(key & 0xFFFFFFFFull));

        float4 mp = ld4(props + ((size_t)bb * NN + idx) * 4);
        float4 gb = ld4(gts + ((size_t)bb * GG + g) * 4);

        float pw  = mp.z - mp.x;
        float ph  = mp.w - mp.y;
        float pcx = fmaf(0.5f, pw, mp.x);
        float pcy = fmaf(0.5f, ph, mp.y);
        float gw  = gb.z - gb.x;
        float gh  = gb.w - gb.y;
        float gcx = fmaf(0.5f, gw, gb.x);
        float gcy = fmaf(0.5f, gh, gb.y);

        float dx = __fdividef(10.0f * (gcx - pcx), pw);
        float dy = __fdividef(10.0f * (gcy - pcy), ph);
        float dw = 5.0f * __logf(__fdividef(gw, pw));
        float dh = 5.0f * __logf(__fdividef(gh, ph));

        float* o = out_regt + (size_t)i * 4;
        o[0] = dx; o[1] = dy; o[2] = dw; o[3] = dh;
        out_scores[i] = q;
    }
}

// ---------------------------------------------------------------------------
extern "C" void kernel_launch(void* const* d_in, const int* in_sizes, int n_in,
                              void* d_out, int out_size) {
    const float* props = (const float*)d_in[0];   // (B, N, 4)
    const float* gts   = (const float*)d_in[1];   // (B, G, 4)
    const float* reg   = (const float*)d_in[2];   // (B, N+G, 4)

    float* out        = (float*)d_out;
    float* out_pred   = out;                                  // B*(N+G)*4
    float* out_regt   = out_pred + (size_t)BB * NPG * 4;      // B*G*4
    float* out_scores = out_regt + (size_t)BB * GG * 4;       // B*G
    float* out_labels = out_scores + (size_t)BB * GG;         // B*(N+G)

    dim3 gm(GRID_X, BB);
    iou_kernel<<<gm, 256>>>(props, gts, out_labels);

    decode_kernel<<<gm, 256>>>(props, gts, reg,
                               out_pred, out_regt, out_scores);
}

// round 16
// speedup vs baseline: 1.8426x; 1.1235x over previous
#include <cuda_runtime.h>
#include <math.h>

#define BB   16
#define NN   16000
#define GG   128
#define NPG  (NN + GG)          /* 16128 */
#define IMGW 800.0f
#define IMGH 800.0f
#define XCLIP 4.135166556742356f   /* log(1000/16) */
#define MAXWH 64.0f             /* boxes are at most 64px wide/tall */

#define NBX   12                /* 12x12 bins */
#define NBINS (NBX * NBX)
#define BINW_INV (12.0f / 800.0f)

#define ITPB   512              /* iou: threads per block */
#define IGRIDX 32               /* 32*512 = 16384 >= 16128 */

#define DGRIDX (NPG / 256)      /* decode: 63 */

// Per-GT argmax keys: (q_bits<<32) | (0xFFFFFFFF - idx).
// Zero at module load == "no hit"; decode_kernel consumes AND re-zeroes each
// call so every graph replay starts clean.
__device__ unsigned long long g_keys[BB * GG];

__device__ __forceinline__ float4 ld4(const float* p) {
    return *reinterpret_cast<const float4*>(p);
}

// ---------------------------------------------------------------------------
// Kernel 1: IoU — labels + per-GT argmax (exact IoU via atomicMax).
// 512-thread blocks: half as many prologues (GT load + bin build + barriers)
// for the same resident-warp count. Both LDGs issued at kernel top so DRAM
// latency overlaps the mask zeroing.
// ---------------------------------------------------------------------------
__global__ void __launch_bounds__(ITPB)
iou_kernel(const float* __restrict__ props,
           const float* __restrict__ gts,
           float* __restrict__ out_labels) {
    __shared__ float4 sg[GG];
    __shared__ uint4  smask[NBINS];

    const int b   = blockIdx.y;
    const int tid = threadIdx.x;
    const int p   = blockIdx.x * ITPB + tid;
    const float* gt_b = gts + (size_t)b * GG * 4;

    // issue long-latency loads FIRST (independent of smem zeroing)
    float4 gtv;
    if (tid < GG) gtv = ld4(gt_b + tid * 4);
    float4 a;
    if (p < NN) a = ld4(props + ((size_t)b * NN + p) * 4);

    // zero bin masks (144 uint4 over 512 threads)
    if (tid < NBINS) smask[tid] = make_uint4(0u, 0u, 0u, 0u);
    __syncthreads();

    // ---- prologue: GT boxes -> smem + corner-bin masks (dilated 64px) ----
    if (tid < GG) {
        sg[tid] = gtv;
        int bx0 = (int)(fmaxf(gtv.x - MAXWH, 0.0f) * BINW_INV);
        int bx1 = (int)(gtv.z * BINW_INV); if (bx1 > NBX - 1) bx1 = NBX - 1;
        int by0 = (int)(fmaxf(gtv.y - MAXWH, 0.0f) * BINW_INV);
        int by1 = (int)(gtv.w * BINW_INV); if (by1 > NBX - 1) by1 = NBX - 1;
        const unsigned bit  = 1u << (tid & 31);
        const int      word = tid >> 5;
        unsigned int* base = reinterpret_cast<unsigned int*>(smask);
        for (int by = by0; by <= by1; by++)
            for (int bx = bx0; bx <= bx1; bx++)
                atomicOr(base + (by * NBX + bx) * 4 + word, bit);
    }
    __syncthreads();

    if (p >= NPG) return;

    float label;
    if (p >= NN) {
        label = 1.0f;   // appended GT: self-IoU == 1.0, not in argmax domain
    } else {
        const float area_a = __fmul_rn(__fsub_rn(a.z, a.x), __fsub_rn(a.w, a.y));
        float vmax = 0.0f;
        unsigned long long* keyrow = g_keys + b * GG;
        const unsigned low = 0xFFFFFFFFu - (unsigned)p;

        const int bin = (int)(a.y * BINW_INV) * NBX + (int)(a.x * BINW_INV);
        uint4 m4 = smask[bin];
        unsigned long long m0 = ((unsigned long long)m4.y << 32) | m4.x;
        unsigned long long m1 = ((unsigned long long)m4.w << 32) | m4.z;

        for (;;) {
            int g;
            if      (m0) { g =      __ffsll(m0) - 1; m0 &= m0 - 1; }
            else if (m1) { g = 63 + __ffsll(m1);     m1 &= m1 - 1; }
            else break;

            float4 gb = sg[g];
            float ltx = fmaxf(a.x, gb.x);
            float lty = fmaxf(a.y, gb.y);
            float rbx = fminf(a.z, gb.z);
            float rby = fminf(a.w, gb.w);
            float ww = __fsub_rn(rbx, ltx);
            float hh = __fsub_rn(rby, lty);
            if (ww > 0.0f && hh > 0.0f) {
                float area_b = __fmul_rn(__fsub_rn(gb.z, gb.x),
                                         __fsub_rn(gb.w, gb.y));
                float inter = __fmul_rn(ww, hh);
                float uni   = __fsub_rn(__fadd_rn(area_b, area_a), inter);
                float q     = __fdiv_rn(inter, uni);
                vmax = fmaxf(vmax, q);
                unsigned long long key =
                    ((unsigned long long)__float_as_uint(q) << 32) | low;
                atomicMax(keyrow + g, key);
            }
        }
        label = (vmax >= 0.5f) ? 1.0f : 0.0f;
    }
    out_labels[(size_t)b * NPG + p] = label;
}

// ---------------------------------------------------------------------------
// Kernel 2: decode+clip for all B*(N+G) boxes; its first 8 blocks (y==0)
// also run the 2048-item encode epilogue (keys -> reg_targets + roi_scores,
// then key reset). No third launch.
// ---------------------------------------------------------------------------
__global__ void __launch_bounds__(256)
decode_kernel(const float* __restrict__ props,
              const float* __restrict__ gts,
              const float* __restrict__ reg,
              float* __restrict__ out_pred,
              float* __restrict__ out_regt,
              float* __restrict__ out_scores) {
    const int b   = blockIdx.y;
    const int tid = threadIdx.x;
    const int p   = blockIdx.x * 256 + tid;

    // ---- decode + clip (outputs only: fast math) ----
    {
        float4 a = (p < NN) ? ld4(props + ((size_t)b * NN + p) * 4)
                            : ld4(gts + ((size_t)b * GG + (p - NN)) * 4);
        float4 r = ld4(reg + ((size_t)b * NPG + p) * 4);
        float pw  = a.z - a.x;
        float ph  = a.w - a.y;
        float pcx = fmaf(0.5f, pw, a.x);
        float pcy = fmaf(0.5f, ph, a.y);
        float dx = r.x * 0.1f;
        float dy = r.y * 0.1f;
        float dw = fminf(r.z * 0.2f, XCLIP);
        float dh = fminf(r.w * 0.2f, XCLIP);
        float ncx = fmaf(dx, pw, pcx);
        float ncy = fmaf(dy, ph, pcy);
        float hnw = 0.5f * __expf(dw) * pw;
        float hnh = 0.5f * __expf(dh) * ph;
        float4 o;
        o.x = fminf(fmaxf(ncx - hnw, 0.0f), IMGW);
        o.y = fminf(fmaxf(ncy - hnh, 0.0f), IMGH);
        o.z = fminf(fmaxf(ncx + hnw, 0.0f), IMGW);
        o.w = fminf(fmaxf(ncy + hnh, 0.0f), IMGH);
        *reinterpret_cast<float4*>(out_pred + ((size_t)b * NPG + p) * 4) = o;
    }

    // ---- encode epilogue, folded into the first 8 blocks ----
    if (blockIdx.y == 0 && blockIdx.x < 8) {
        int i  = blockIdx.x * 256 + tid;     // i < 2048 = BB*GG
        int bb = i >> 7;
        int g  = i & (GG - 1);

        unsigned long long key = __ldcg(&g_keys[i]);
        __stcg(&g_keys[i], 0ull);            // reset for next graph replay
        float q = __uint_as_float((unsigned)(key >> 32));
        unsigned idx = (key == 0ull) ? 0u
                     : (0xFFFFFFFFu - (unsigned)(key & 0xFFFFFFFFull));

        float4 mp = ld4(props + ((size_t)bb * NN + idx) * 4);
        float4 gb = ld4(gts + ((size_t)bb * GG + g) * 4);

        float pw  = mp.z - mp.x;
        float ph  = mp.w - mp.y;
        float pcx = fmaf(0.5f, pw, mp.x);
        float pcy = fmaf(0.5f, ph, mp.y);
        float gw  = gb.z - gb.x;
        float gh  = gb.w - gb.y;
        float gcx = fmaf(0.5f, gw, gb.x);
        float gcy = fmaf(0.5f, gh, gb.y);

        float dx = __fdividef(10.0f * (gcx - pcx), pw);
        float dy = __fdividef(10.0f * (gcy - pcy), ph);
        float dw = 5.0f * __logf(__fdividef(gw, pw));
        float dh = 5.0f * __logf(__fdividef(gh, ph));

        float* o = out_regt + (size_t)i * 4;
        o[0] = dx; o[1] = dy; o[2] = dw; o[3] = dh;
        out_scores[i] = q;
    }
}

// ---------------------------------------------------------------------------
extern "C" void kernel_launch(void* const* d_in, const int* in_sizes, int n_in,
                              void* d_out, int out_size) {
    const float* props = (const float*)d_in[0];   // (B, N, 4)
    const float* gts   = (const float*)d_in[1];   // (B, G, 4)
    const float* reg   = (const float*)d_in[2];   // (B, N+G, 4)

    float* out        = (float*)d_out;
    float* out_pred   = out;                                  // B*(N+G)*4
    float* out_regt   = out_pred + (size_t)BB * NPG * 4;      // B*G*4
    float* out_scores = out_regt + (size_t)BB * GG * 4;       // B*G
    float* out_labels = out_scores + (size_t)BB * GG;         // B*(N+G)

    dim3 gi(IGRIDX, BB);
    iou_kernel<<<gi, ITPB>>>(props, gts, out_labels);

    dim3 gd(DGRIDX, BB);
    decode_kernel<<<gd, 256>>>(props, gts, reg,
                               out_pred, out_regt, out_scores);
}